// round 9
// baseline (speedup 1.0000x reference)
#include <cuda_runtime.h>
#include <cuda_fp16.h>

#define NN 50000
#define NE 600000
#define FI 128
#define HD 64
#define NC 40
#define SCB 512
#define NBLK ((NN + SCB - 1) / SCB)   // 98
#define KH 10

#define PB  592                       // 148 SMs x 4 blocks (register-guaranteed co-resident)
#define PW  (PB * 8)                  // 4736 warps
#define RPW 11                        // ceil(NN / PW)

// ---------------- device scratch (static, allocation-free) ----------------
__device__ float   g_x1[NN * HD];     // x @ W1 (fp32, for final)
__device__ __half2 g_sA[NN * 32];     // fp16 ping
__device__ __half2 g_sB[NN * 32];     // fp16 pong
__device__ float   g_deg[NN];
__device__ float   g_dinv[NN];
__device__ int     g_cnt[NN];
__device__ int     g_fill[NN];
__device__ int     g_rowptr[NN + 1];
__device__ int     g_bsum[NBLK];
__device__ int     g_bar[KH];         // inter-hop barrier counters (zeroed per launch)
__device__ float2  g_edge[NE];        // (col as int bits, normalized weight)

// ---------------- preprocessing ----------------
__global__ void k_init() {
    int i = blockIdx.x * blockDim.x + threadIdx.x;
    if (i < NN) { g_deg[i] = 1.0f; g_cnt[i] = 0; g_fill[i] = 0; }
    if (i < KH) g_bar[i] = 0;
}

__global__ void k_degree(const int* __restrict__ ei, const float* __restrict__ ew) {
    int e = blockIdx.x * blockDim.x + threadIdx.x;
    if (e < NE) {
        int r = ei[e];
        atomicAdd(&g_deg[r], ew[e]);
        atomicAdd(&g_cnt[r], 1);
    }
}

// Stage A: per-block exclusive scan of g_cnt -> g_rowptr (pre-offset) + dinv fused.
__global__ void __launch_bounds__(SCB) k_scanA() {
    __shared__ int wsum[16];
    int t = threadIdx.x;
    int i = blockIdx.x * SCB + t;
    int v = (i < NN) ? g_cnt[i] : 0;
    if (i < NN) {
        float d = g_deg[i];
        g_dinv[i] = (d > 0.0f) ? rsqrtf(fmaxf(d, 1e-12f)) : 0.0f;
    }
    int lane = t & 31, w = t >> 5;
    int inc = v;
#pragma unroll
    for (int o = 1; o < 32; o <<= 1) {
        int u = __shfl_up_sync(0xFFFFFFFFu, inc, o);
        if (lane >= o) inc += u;
    }
    if (lane == 31) wsum[w] = inc;
    __syncthreads();
    if (w == 0) {
        int s = (lane < 16) ? wsum[lane] : 0;
#pragma unroll
        for (int o = 1; o < 16; o <<= 1) {
            int u = __shfl_up_sync(0xFFFFFFFFu, s, o);
            if (lane >= o) s += u;
        }
        if (lane < 16) wsum[lane] = s;
    }
    __syncthreads();
    int wbase = (w > 0) ? wsum[w - 1] : 0;
    if (i < NN) g_rowptr[i] = wbase + inc - v;
    if (t == 0) g_bsum[blockIdx.x] = wsum[15];
}

// Merged stage B+C: each block computes its own offset and applies it.
__global__ void __launch_bounds__(SCB) k_scanBC() {
    __shared__ int s_off;
    int t = threadIdx.x;
    int b = blockIdx.x;
    if (t == 0) s_off = 0;
    __syncthreads();
    if (t < b) atomicAdd(&s_off, g_bsum[t]);
    __syncthreads();
    int i = b * SCB + t;
    if (i < NN) g_rowptr[i] += s_off;
    if (b == 0 && t == 0) g_rowptr[NN] = NE;
}

__global__ void k_fill(const int* __restrict__ ei, const float* __restrict__ ew) {
    int e = blockIdx.x * blockDim.x + threadIdx.x;
    if (e < NE) {
        int r = ei[e];
        int c = ei[NE + e];
        float w = ew[e] * g_dinv[r] * g_dinv[c];
        int p = g_rowptr[r] + atomicAdd(&g_fill[r], 1);
        g_edge[p] = make_float2(__int_as_float(c), w);
    }
}

// ---------------- GEMM1: x1 = x @ W1; writes fp32 g_x1 and fp16 g_sA ----------------
__global__ void __launch_bounds__(256) k_gemm1(const float* __restrict__ x,
                                               const float* __restrict__ W1) {
    __shared__ float W1s[64 * 64];
    __shared__ float xs[64 * 68];
    int t  = threadIdx.x;
    int tx = t & 15;
    int ty = t >> 4;
    int nb = blockIdx.x * 64;

    float acc[4][4];
#pragma unroll
    for (int i = 0; i < 4; i++)
#pragma unroll
        for (int j = 0; j < 4; j++) acc[i][j] = 0.0f;

    for (int kh = 0; kh < 2; kh++) {
        __syncthreads();
        for (int i = t; i < 1024; i += 256)
            ((float4*)W1s)[i] = ((const float4*)(W1 + kh * 64 * 64))[i];
        for (int i = t; i < 1024; i += 256) {
            int r  = i >> 4;
            int kk = (i & 15) << 2;
            int n  = nb + r;
            float4 v = make_float4(0.f, 0.f, 0.f, 0.f);
            if (n < NN) v = *(const float4*)(x + n * FI + kh * 64 + kk);
            *(float4*)(xs + r * 68 + kk) = v;
        }
        __syncthreads();
#pragma unroll 8
        for (int k = 0; k < 64; k++) {
            float4 b4 = *(const float4*)(W1s + k * 64 + tx * 4);
#pragma unroll
            for (int i = 0; i < 4; i++) {
                float a = xs[(ty * 4 + i) * 68 + k];
                acc[i][0] += a * b4.x;
                acc[i][1] += a * b4.y;
                acc[i][2] += a * b4.z;
                acc[i][3] += a * b4.w;
            }
        }
    }
#pragma unroll
    for (int i = 0; i < 4; i++) {
        int n = nb + ty * 4 + i;
        if (n < NN) {
            *(float4*)(g_x1 + n * HD + tx * 4) =
                make_float4(acc[i][0], acc[i][1], acc[i][2], acc[i][3]);
            g_sA[n * 32 + tx * 2]     = __floats2half2_rn(acc[i][0], acc[i][1]);
            g_sA[n * 32 + tx * 2 + 1] = __floats2half2_rn(acc[i][2], acc[i][3]);
        }
    }
}

// ---------------- persistent: 10 hops, acc in REGISTERS, fused final MLP ------------
__global__ void __launch_bounds__(256, 4) k_prop(const float* __restrict__ b1,
                                                 const float* __restrict__ W2,
                                                 const float* __restrict__ b2,
                                                 float* __restrict__ out) {
    __shared__ float s_w2[HD * NC];   // 10.2 KB (loaded after hop phase)
    __shared__ float s_z[8][64];
    __shared__ float s_b1[HD];

    int t = threadIdx.x, w = t >> 5, lane = t & 31;
    int wg = blockIdx.x * 8 + w;

    float accx[RPW], accy[RPW];
#pragma unroll
    for (int k = 0; k < RPW; k++) { accx[k] = 0.0f; accy[k] = 0.0f; }

    for (int l = 0; l < KH; l++) {
        const __half2* __restrict__ src = (l & 1) ? g_sB : g_sA;
        __half2* __restrict__ dst = (l & 1) ? g_sA : g_sB;
        int last = (l == KH - 1);

#pragma unroll
        for (int k = 0; k < RPW; k++) {
            int r = wg + k * PW;
            if (r < NN) {
                int beg = g_rowptr[r];       // L1-hot after hop 0
                int end = g_rowptr[r + 1];
                float di = g_dinv[r];
                float sw = di * di;
                float2 self = __half22float2(__ldcg(&src[r * 32 + lane]));
                float ax = sw * self.x;
                float ay = sw * self.y;

                int e = beg;
                for (; e + 3 < end; e += 4) {
                    float2 cw0 = g_edge[e];
                    float2 cw1 = g_edge[e + 1];
                    float2 cw2 = g_edge[e + 2];
                    float2 cw3 = g_edge[e + 3];
                    float2 h0 = __half22float2(__ldcg(&src[__float_as_int(cw0.x) * 32 + lane]));
                    float2 h1 = __half22float2(__ldcg(&src[__float_as_int(cw1.x) * 32 + lane]));
                    float2 h2 = __half22float2(__ldcg(&src[__float_as_int(cw2.x) * 32 + lane]));
                    float2 h3 = __half22float2(__ldcg(&src[__float_as_int(cw3.x) * 32 + lane]));
                    ax += cw0.y * h0.x + cw1.y * h1.x;
                    ay += cw0.y * h0.y + cw1.y * h1.y;
                    ax += cw2.y * h2.x + cw3.y * h3.x;
                    ay += cw2.y * h2.y + cw3.y * h3.y;
                }
                for (; e < end; e++) {
                    float2 cw = g_edge[e];
                    float2 h0 = __half22float2(__ldcg(&src[__float_as_int(cw.x) * 32 + lane]));
                    ax += cw.y * h0.x;
                    ay += cw.y * h0.y;
                }

                if (!last)
                    __stcg(&dst[r * 32 + lane], __floats2half2_rn(ax, ay));
                accx[k] += ax;
                accy[k] += ay;
            }
        }

        if (!last) {
            __threadfence();
            __syncthreads();
            if (t == 0) {
                atomicAdd(&g_bar[l], 1);
                while (*((volatile int*)&g_bar[l]) < PB) __nanosleep(32);
            }
            __syncthreads();
        }
    }

    // ---------- fused final: z = relu(C1*acc + C2*x1 + b1); out = z @ W2 + b2 ----------
    for (int i = t; i < HD * NC; i += 256) s_w2[i] = W2[i];
    if (t < HD) s_b1[t] = b1[t];
    __syncthreads();

    const float C1 = (1.0f - 0.1f) / (float)KH;  // 0.09
    const float C2 = 0.1f;

#pragma unroll
    for (int k = 0; k < RPW; k++) {
        int r = wg + k * PW;
        if (r < NN) {
            float2 x1v = ((const float2*)g_x1)[r * 32 + lane];
            s_z[w][2 * lane]     = fmaxf(C1 * accx[k] + C2 * x1v.x + s_b1[2 * lane],     0.0f);
            s_z[w][2 * lane + 1] = fmaxf(C1 * accy[k] + C2 * x1v.y + s_b1[2 * lane + 1], 0.0f);
            __syncwarp();

            float d0 = 0.0f, d1 = 0.0f;
#pragma unroll 8
            for (int kk = 0; kk < 64; kk++) {
                float z = s_z[w][kk];
                d0 += z * s_w2[kk * NC + lane];
                if (lane < 8) d1 += z * s_w2[kk * NC + 32 + lane];
            }
            out[r * NC + lane] = d0 + b2[lane];
            if (lane < 8) out[r * NC + 32 + lane] = d1 + b2[32 + lane];
            __syncwarp();
        }
    }
}

// ---------------- launch ----------------
extern "C" void kernel_launch(void* const* d_in, const int* in_sizes, int n_in,
                              void* d_out, int out_size) {
    const float* x  = (const float*)d_in[0];
    const int*   ei = (const int*)d_in[1];    // [2, NE]
    const float* ew = (const float*)d_in[2];
    const float* W1 = (const float*)d_in[3];  // [128, 64]
    const float* b1 = (const float*)d_in[4];
    const float* W2 = (const float*)d_in[5];  // [64, 40]
    const float* b2 = (const float*)d_in[6];
    float* out = (float*)d_out;

    k_init  <<<(NN + 255) / 256, 256>>>();
    k_degree<<<(NE + 255) / 256, 256>>>(ei, ew);
    k_scanA <<<NBLK, SCB>>>();
    k_scanBC<<<NBLK, SCB>>>();
    k_fill  <<<(NE + 255) / 256, 256>>>(ei, ew);
    k_gemm1 <<<(NN + 63) / 64, 256>>>(x, W1);
    k_prop  <<<PB, 256>>>(b1, W2, b2, out);
}

// round 10
// speedup vs baseline: 1.1388x; 1.1388x over previous
#include <cuda_runtime.h>
#include <cuda_fp16.h>

#define NN 50000
#define NE 600000
#define FI 128
#define HD 64
#define NC 40
#define NBLK 98                       // scan tiles of 512 nodes
#define KH 10

#define PPB 256                       // preproc threads/block
#define PPG 592                       // preproc grid (148 SMs x 4, co-resident)

// ---------------- device scratch (static, allocation-free) ----------------
__device__ float   g_x1[NN * HD];     // x @ W1 (fp32, for final)
__device__ __half2 g_sA[NN * 32];     // fp16 ping
__device__ __half2 g_sB[NN * 32];     // fp16 pong
__device__ float   g_acc[NN * HD];    // fp32 running sum of T^l x1
__device__ float   g_deg[NN];
__device__ float   g_dinv[NN];
__device__ int     g_cnt[NN];
__device__ int     g_fill[NN];
__device__ int     g_rowptr[NN + 1];
__device__ int     g_bsum[NBLK];
__device__ int     g_bar[4];          // preproc barrier counters (zeroed each replay)
__device__ float2  g_edge[NE];        // (col as int bits, normalized weight)

// ---------------- launch 0: zero state ----------------
__global__ void k_zero() {
    int i = blockIdx.x * blockDim.x + threadIdx.x;
    if (i < NN) { g_deg[i] = 1.0f; g_cnt[i] = 0; g_fill[i] = 0; }
    if (i < 4) g_bar[i] = 0;
}

// ---------------- launch 1: degree + scan + fill, one kernel ----------------
__device__ __forceinline__ void gbar(int l, int t) {
    __threadfence();
    __syncthreads();
    if (t == 0) {
        atomicAdd(&g_bar[l], 1);
        while (*((volatile int*)&g_bar[l]) < PPG) __nanosleep(32);
    }
    __syncthreads();
}

__global__ void __launch_bounds__(PPB) k_pre(const int* __restrict__ ei,
                                             const float* __restrict__ ew) {
    int t = threadIdx.x, b = blockIdx.x;
    int gtid = b * PPB + t;
    const int gsz = PPG * PPB;        // 151552

    // phase 1: degree accumulation
    for (int e = gtid; e < NE; e += gsz) {
        int r = ei[e];
        atomicAdd(&g_deg[r], ew[e]);
        atomicAdd(&g_cnt[r], 1);
    }
    gbar(0, t);

    // phase 2a: dinv (all blocks) + local scan (blocks 0..97, 512 nodes each)
    for (int i = gtid; i < NN; i += gsz) {
        float d = g_deg[i];
        g_dinv[i] = (d > 0.0f) ? rsqrtf(fmaxf(d, 1e-12f)) : 0.0f;
    }
    __shared__ int wsum[8];
    int v0 = 0, v1 = 0;
    if (b < NBLK) {
        int i0 = b * 512 + 2 * t;
        int i1 = i0 + 1;
        v0 = (i0 < NN) ? g_cnt[i0] : 0;
        v1 = (i1 < NN) ? g_cnt[i1] : 0;
        int pair = v0 + v1;
        int lane = t & 31, w = t >> 5;
        int inc = pair;
#pragma unroll
        for (int o = 1; o < 32; o <<= 1) {
            int u = __shfl_up_sync(0xFFFFFFFFu, inc, o);
            if (lane >= o) inc += u;
        }
        if (lane == 31) wsum[w] = inc;
        __syncthreads();
        if (w == 0 && lane < 8) {
            int s = wsum[lane];
#pragma unroll
            for (int o = 1; o < 8; o <<= 1) {
                int u = __shfl_up_sync(0x000000FFu, s, o);
                if (lane >= o) s += u;
            }
            wsum[lane] = s;
        }
        __syncthreads();
        int base = (w > 0) ? wsum[w - 1] : 0;
        int excl = base + inc - pair;     // exclusive prefix of pairs
        if (i0 < NN) g_rowptr[i0] = excl;
        if (i1 < NN) g_rowptr[i1] = excl + v0;
        if (t == 0) g_bsum[b] = wsum[7];
    }
    gbar(1, t);

    // phase 2b: apply inter-tile offsets
    if (b < NBLK) {
        __shared__ int s_off;
        if (t == 0) s_off = 0;
        __syncthreads();
        if (t < b) atomicAdd(&s_off, g_bsum[t]);   // b <= 97 < 256
        __syncthreads();
        int i0 = b * 512 + 2 * t;
        int i1 = i0 + 1;
        if (i0 < NN) g_rowptr[i0] += s_off;
        if (i1 < NN) g_rowptr[i1] += s_off;
        if (b == 0 && t == 0) g_rowptr[NN] = NE;
    }
    gbar(2, t);

    // phase 3: CSR fill
    for (int e = gtid; e < NE; e += gsz) {
        int r = ei[e];
        int c = ei[NE + e];
        float w = ew[e] * g_dinv[r] * g_dinv[c];
        int p = g_rowptr[r] + atomicAdd(&g_fill[r], 1);
        g_edge[p] = make_float2(__int_as_float(c), w);
    }
}

// ---------------- launch 2: GEMM1 x1 = x @ W1; writes fp32 g_x1 and fp16 g_sA --------
__global__ void __launch_bounds__(256) k_gemm1(const float* __restrict__ x,
                                               const float* __restrict__ W1) {
    __shared__ float W1s[64 * 64];
    __shared__ float xs[64 * 68];
    int t  = threadIdx.x;
    int tx = t & 15;
    int ty = t >> 4;
    int nb = blockIdx.x * 64;

    float acc[4][4];
#pragma unroll
    for (int i = 0; i < 4; i++)
#pragma unroll
        for (int j = 0; j < 4; j++) acc[i][j] = 0.0f;

    for (int kh = 0; kh < 2; kh++) {
        __syncthreads();
        for (int i = t; i < 1024; i += 256)
            ((float4*)W1s)[i] = ((const float4*)(W1 + kh * 64 * 64))[i];
        for (int i = t; i < 1024; i += 256) {
            int r  = i >> 4;
            int kk = (i & 15) << 2;
            int n  = nb + r;
            float4 v = make_float4(0.f, 0.f, 0.f, 0.f);
            if (n < NN) v = *(const float4*)(x + n * FI + kh * 64 + kk);
            *(float4*)(xs + r * 68 + kk) = v;
        }
        __syncthreads();
#pragma unroll 8
        for (int k = 0; k < 64; k++) {
            float4 b4 = *(const float4*)(W1s + k * 64 + tx * 4);
#pragma unroll
            for (int i = 0; i < 4; i++) {
                float a = xs[(ty * 4 + i) * 68 + k];
                acc[i][0] += a * b4.x;
                acc[i][1] += a * b4.y;
                acc[i][2] += a * b4.z;
                acc[i][3] += a * b4.w;
            }
        }
    }
#pragma unroll
    for (int i = 0; i < 4; i++) {
        int n = nb + ty * 4 + i;
        if (n < NN) {
            *(float4*)(g_x1 + n * HD + tx * 4) =
                make_float4(acc[i][0], acc[i][1], acc[i][2], acc[i][3]);
            g_sA[n * 32 + tx * 2]     = __floats2half2_rn(acc[i][0], acc[i][1]);
            g_sA[n * 32 + tx * 2 + 1] = __floats2half2_rn(acc[i][2], acc[i][3]);
        }
    }
}

// ---------------- SpMM hop (R5-identical): warp per row, unroll 4, fused acc RMW ----
__global__ void __launch_bounds__(256) k_hop(int srcA, int first) {
    int gw   = (blockIdx.x * blockDim.x + threadIdx.x) >> 5;
    int lane = threadIdx.x & 31;
    if (gw >= NN) return;

    const __half2* __restrict__ s = srcA ? g_sA : g_sB;
    __half2* __restrict__ d = srcA ? g_sB : g_sA;

    int beg = g_rowptr[gw];
    int end = g_rowptr[gw + 1];

    float di = g_dinv[gw];
    float sw = di * di;                   // self-loop weight
    float2 self = __half22float2(s[gw * 32 + lane]);
    float ax = sw * self.x;
    float ay = sw * self.y;

    int e = beg;
    for (; e + 3 < end; e += 4) {
        float2 cw0 = g_edge[e];
        float2 cw1 = g_edge[e + 1];
        float2 cw2 = g_edge[e + 2];
        float2 cw3 = g_edge[e + 3];
        float2 h0 = __half22float2(s[__float_as_int(cw0.x) * 32 + lane]);
        float2 h1 = __half22float2(s[__float_as_int(cw1.x) * 32 + lane]);
        float2 h2 = __half22float2(s[__float_as_int(cw2.x) * 32 + lane]);
        float2 h3 = __half22float2(s[__float_as_int(cw3.x) * 32 + lane]);
        ax += cw0.y * h0.x + cw1.y * h1.x;
        ay += cw0.y * h0.y + cw1.y * h1.y;
        ax += cw2.y * h2.x + cw3.y * h3.x;
        ay += cw2.y * h2.y + cw3.y * h3.y;
    }
    for (; e < end; e++) {
        float2 cw = g_edge[e];
        float2 h0 = __half22float2(s[__float_as_int(cw.x) * 32 + lane]);
        ax += cw.y * h0.x;
        ay += cw.y * h0.y;
    }

    d[gw * 32 + lane] = __floats2half2_rn(ax, ay);
    float2* ac = (float2*)g_acc;
    if (first) {
        ac[gw * 32 + lane] = make_float2(ax, ay);
    } else {
        float2 p = ac[gw * 32 + lane];
        ac[gw * 32 + lane] = make_float2(p.x + ax, p.y + ay);
    }
}

// ---------------- final (R5-identical) ----------------
__global__ void __launch_bounds__(320) k_final(const float* __restrict__ b1,
                                               const float* __restrict__ W2,
                                               const float* __restrict__ b2,
                                               float* __restrict__ out) {
    __shared__ float W2t[NC * 68];
    __shared__ float zs[8 * 64];
    __shared__ float b1s[HD];

    int t = threadIdx.x;
    for (int i = t; i < HD * NC; i += 320) {
        int k = i / NC, c = i % NC;
        W2t[c * 68 + k] = W2[i];
    }
    if (t < HD) b1s[t] = b1[t];

    int node = t / NC;
    int cls  = t % NC;
    float b2v = b2[cls];
    __syncthreads();

    const float C1 = (1.0f - 0.1f) / 10.0f;  // 0.09
    const float C2 = 0.1f;
    int nb0 = blockIdx.x * 400;

    for (int it = 0; it < 50; it++) {
        int nb = nb0 + it * 8;
        {
            int i = t;
            int n = nb + (i >> 6), f = i & 63;
            zs[i] = fmaxf(C1 * g_acc[n * HD + f] + C2 * g_x1[n * HD + f] + b1s[f], 0.0f);
            i = t + 320;
            if (i < 512) {
                n = nb + (i >> 6); f = i & 63;
                zs[i] = fmaxf(C1 * g_acc[n * HD + f] + C2 * g_x1[n * HD + f] + b1s[f], 0.0f);
            }
        }
        __syncthreads();
        float s = b2v;
        const float* zr = zs + node * 64;
        const float* wr = W2t + cls * 68;
#pragma unroll
        for (int k = 0; k < 64; k += 4) {
            float4 zv = *(const float4*)(zr + k);
            float4 wv = *(const float4*)(wr + k);
            s += zv.x * wv.x + zv.y * wv.y + zv.z * wv.z + zv.w * wv.w;
        }
        out[(nb + node) * NC + cls] = s;
        __syncthreads();
    }
}

// ---------------- launch ----------------
extern "C" void kernel_launch(void* const* d_in, const int* in_sizes, int n_in,
                              void* d_out, int out_size) {
    const float* x  = (const float*)d_in[0];
    const int*   ei = (const int*)d_in[1];    // [2, NE]
    const float* ew = (const float*)d_in[2];
    const float* W1 = (const float*)d_in[3];  // [128, 64]
    const float* b1 = (const float*)d_in[4];
    const float* W2 = (const float*)d_in[5];  // [64, 40]
    const float* b2 = (const float*)d_in[6];
    float* out = (float*)d_out;

    k_zero <<<(NN + 255) / 256, 256>>>();          // launch 0
    k_pre  <<<PPG, PPB>>>(ei, ew);                 // launch 1
    k_gemm1<<<(NN + 63) / 64, 256>>>(x, W1);       // launch 2

    int hop_blocks = (NN * 32 + 255) / 256;        // 6250
    for (int i = 0; i < KH; i++)                   // launches 3..12 (hop0 = ncu target)
        k_hop<<<hop_blocks, 256>>>((i & 1) == 0, i == 0);

    k_final<<<125, 320>>>(b1, W2, b2, out);
}